// round 17
// baseline (speedup 1.0000x reference)
#include <cuda_runtime.h>
#include <cuda_bf16.h>
#include <math.h>
#include <cstdint>

#define NUM_NODES 9
#define HIDDEN    512
#define BATCH     8192
#define M_ROWS    (BATCH * NUM_NODES)   // 73728
#define EPS       1e-8f

#define NSTREAMS        4
#define NCHUNKS         8
#define BATCH_PER_CHUNK (BATCH / NCHUNKS)              // 1024
#define ROWS_PER_CHUNK  (BATCH_PER_CHUNK * NUM_NODES)  // 9216 = 72 * 128

// Scratch buffers (device globals; no dynamic alloc allowed).
__device__ float g_scratch[(size_t)M_ROWS * HIDDEN];   // x_proj -> h -> mobius out (tf32+perm)
__device__ float g_w1[HIDDEN * HIDDEN];                // tf32-rounded to_w
__device__ float g_w2[HIDDEN * HIDDEN];                // tf32-rounded + k-permuted from_w
__device__ float g_yy[NUM_NODES * NUM_NODES];          // ||mw[i][j]||^2

__device__ __forceinline__ uint32_t smem_u32(const void* p) {
    uint32_t a;
    asm("{ .reg .u64 t; cvta.to.shared.u64 t, %1; cvt.u32.u64 %0, t; }" : "=r"(a) : "l"(p));
    return a;
}
__device__ __forceinline__ uint32_t cvt_tf32(float f) {
    uint32_t u;
    asm("cvt.rna.tf32.f32 %0, %1;" : "=r"(u) : "f"(f));
    return u;
}

#define CP_ASYNC16(saddr, gptr) \
    asm volatile("cp.async.cg.shared.global [%0], [%1], 16;" :: "r"(saddr), "l"(gptr) : "memory")
#define CP_COMMIT() asm volatile("cp.async.commit_group;" ::: "memory")
#define CP_WAIT(n)  asm volatile("cp.async.wait_group %0;" :: "n"(n) : "memory")

__device__ __forceinline__ void mma_tf32(float* d, const uint32_t* a, const uint32_t* b) {
    asm volatile(
        "mma.sync.aligned.m16n8k8.row.col.f32.tf32.tf32.f32 "
        "{%0,%1,%2,%3}, {%4,%5,%6,%7}, {%8,%9}, {%0,%1,%2,%3};"
        : "+f"(d[0]), "+f"(d[1]), "+f"(d[2]), "+f"(d[3])
        : "r"(a[0]), "r"(a[1]), "r"(a[2]), "r"(a[3]), "r"(b[0]), "r"(b[1]));
}

// k-pair permutation within each octet: order [0,4,1,5,2,6,3,7]
__device__ __forceinline__ int kperm(int k7) {
    return (k7 < 4) ? 2 * k7 : 2 * (k7 - 4) + 1;
}

// ---------------------------------------------------------------------------
// Weight prepasses (tiny)
// ---------------------------------------------------------------------------
__global__ void round_kernel(const float4* __restrict__ in, float4* __restrict__ out, int n4) {
    int i = blockIdx.x * blockDim.x + threadIdx.x;
    int stride = gridDim.x * blockDim.x;
    for (; i < n4; i += stride) {
        float4 v = in[i];
        uint4 u = make_uint4(cvt_tf32(v.x), cvt_tf32(v.y), cvt_tf32(v.z), cvt_tf32(v.w));
        out[i] = *(float4*)&u;
    }
}
__global__ void round_perm_kernel(const float* __restrict__ in, float* __restrict__ out, int n) {
    int i = blockIdx.x * blockDim.x + threadIdx.x;
    int stride = gridDim.x * blockDim.x;
    for (; i < n; i += stride) {
        int pos = kperm(i & 7);
        out[(i & ~7) | pos] = __uint_as_float(cvt_tf32(in[i]));
    }
}

// ---------------------------------------------------------------------------
// TF32 mma.sync GEMM, cp.async 2-stage pipeline, __launch_bounds__(128,3).
// CTA 128x128, 128 threads, 4 warps (2M x 2N), warp tile 64x64.  (R15)
// ---------------------------------------------------------------------------
#define BM 128
#define BN 128
#define KCHUNKS (HIDDEN / 32)            // 16
#define STAGES 2

template<bool CVT_A, bool PERM>
__global__ __launch_bounds__(128, 3)
void gemm_cp(const float* __restrict__ A,
             const float* __restrict__ W,
             const float* __restrict__ bias,
             float* __restrict__ C)
{
    constexpr int PITCHF = PERM ? 32 : 36;
    constexpr int TB     = 128 * PITCHF;

    extern __shared__ __align__(16) float smem[];
    const uint32_t smem_base = smem_u32(smem);
    const uint32_t sA0 = smem_base;
    const uint32_t sB0 = smem_base + STAGES * TB * 4;

    const int tid  = threadIdx.x;
    const int bm   = blockIdx.y * BM;
    const int bn   = blockIdx.x * BN;
    const int lane = tid & 31;
    const int wid  = tid >> 5;
    const int m0w  = (wid & 1) * 64;
    const int n0w  = (wid >> 1) * 64;
    const int g    = lane >> 2;
    const int t    = lane & 3;

    const int r = tid >> 3;
    const int q = tid & 7;

    const float* aG = A + (size_t)(bm + r) * HIDDEN + q * 4;
    const float* bG = W + (size_t)(bn + r) * HIDDEN + q * 4;

    uint32_t stOff;
    if (PERM) stOff = (uint32_t)(r * 128 + ((q ^ ((r & 3) << 1)) << 4));
    else      stOff = (uint32_t)(r * PITCHF + q * 4) * 4;
    const uint32_t aS = sA0 + stOff;
    const uint32_t bS = sB0 + stOff;

    float acc[4][8][4];
#pragma unroll
    for (int mi = 0; mi < 4; mi++)
#pragma unroll
        for (int ni = 0; ni < 8; ni++)
#pragma unroll
            for (int e = 0; e < 4; e++) acc[mi][ni][e] = 0.f;

#define ISSUE_STAGE(ck, st) do { \
    const float* _ag = aG + (ck) * 32; \
    const float* _bg = bG + (ck) * 32; \
    uint32_t _as = aS + (uint32_t)(st) * (TB * 4); \
    uint32_t _bs = bS + (uint32_t)(st) * (TB * 4); \
    _Pragma("unroll") \
    for (int _i = 0; _i < 8; _i++) \
        CP_ASYNC16(_as + _i * 16 * PITCHF * 4, _ag + (size_t)_i * 16 * HIDDEN); \
    _Pragma("unroll") \
    for (int _i = 0; _i < 8; _i++) \
        CP_ASYNC16(_bs + _i * 16 * PITCHF * 4, _bg + (size_t)_i * 16 * HIDDEN); \
    CP_COMMIT(); \
} while (0)

    ISSUE_STAGE(0, 0);

#define LDA(v) (CVT_A ? cvt_tf32(v) : __float_as_uint(v))

    for (int ck = 0; ck < KCHUNKS; ck++) {
        const int st = ck & 1;
        CP_WAIT(0);
        __syncthreads();
        if (ck + 1 < KCHUNKS)
            ISSUE_STAGE(ck + 1, st ^ 1);

        const float* cA = smem + st * TB;
        const float* cB = smem + STAGES * TB + st * TB;

#pragma unroll
        for (int s = 0; s < 4; s++) {
            uint32_t af[4][4], bf[8][2];
            if (PERM) {
                const uint32_t c0 =
                    ((uint32_t)(((2 * s + (t >> 1)) ^ ((g & 3) << 1)) << 4)) + ((t & 1) << 3);
                const char* cAb = (const char*)cA;
                const char* cBb = (const char*)cB;
#pragma unroll
                for (int mi = 0; mi < 4; mi++) {
                    const char* p0 = cAb + (m0w + mi * 16 + g) * 128 + c0;
                    uint2 lo = *(const uint2*)p0;
                    uint2 hi = *(const uint2*)(p0 + 8 * 128);
                    af[mi][0] = lo.x; af[mi][2] = lo.y;
                    af[mi][1] = hi.x; af[mi][3] = hi.y;
                }
#pragma unroll
                for (int ni = 0; ni < 8; ni++) {
                    const char* pb = cBb + (n0w + ni * 8 + g) * 128 + c0;
                    uint2 bb = *(const uint2*)pb;
                    bf[ni][0] = bb.x; bf[ni][1] = bb.y;
                }
            } else {
                const int kc = s * 8;
#pragma unroll
                for (int mi = 0; mi < 4; mi++) {
                    const float* ap = cA + (m0w + mi * 16 + g) * PITCHF + kc + t;
                    af[mi][0] = LDA(ap[0]);
                    af[mi][1] = LDA(ap[8 * PITCHF]);
                    af[mi][2] = LDA(ap[4]);
                    af[mi][3] = LDA(ap[8 * PITCHF + 4]);
                }
#pragma unroll
                for (int ni = 0; ni < 8; ni++) {
                    const float* bp = cB + (n0w + ni * 8 + g) * PITCHF + kc + t;
                    bf[ni][0] = __float_as_uint(bp[0]);
                    bf[ni][1] = __float_as_uint(bp[4]);
                }
            }
#pragma unroll
            for (int mi = 0; mi < 4; mi++)
#pragma unroll
                for (int ni = 0; ni < 8; ni++)
                    mma_tf32(acc[mi][ni], af[mi], bf[ni]);
        }
    }
#undef LDA

    // epilogue: bias + store
#pragma unroll
    for (int ni = 0; ni < 8; ni++) {
        const int n = bn + n0w + ni * 8 + t * 2;
        const float b0 = __ldg(&bias[n]);
        const float b1 = __ldg(&bias[n + 1]);
#pragma unroll
        for (int mi = 0; mi < 4; mi++) {
            const int m = bm + m0w + mi * 16 + g;
            float2 v0 = make_float2(acc[mi][ni][0] + b0, acc[mi][ni][1] + b1);
            float2 v1 = make_float2(acc[mi][ni][2] + b0, acc[mi][ni][3] + b1);
            *(float2*)&C[(size_t)m * HIDDEN + n]       = v0;
            *(float2*)&C[(size_t)(m + 8) * HIDDEN + n] = v1;
        }
    }
}

#define DYN_SMEM_G1 (STAGES * 2 * (128 * 36) * 4)   // 73728 B
#define DYN_SMEM_G2 (STAGES * 2 * (128 * 32) * 4)   // 65536 B

// ---------------------------------------------------------------------------
// warp reduction + yy precompute
// ---------------------------------------------------------------------------
__device__ __forceinline__ float warpSum(float v) {
    v += __shfl_xor_sync(0xffffffffu, v, 16);
    v += __shfl_xor_sync(0xffffffffu, v, 8);
    v += __shfl_xor_sync(0xffffffffu, v, 4);
    v += __shfl_xor_sync(0xffffffffu, v, 2);
    v += __shfl_xor_sync(0xffffffffu, v, 1);
    return v;
}

__global__ void yy_kernel(const float* __restrict__ mw) {
    const int idx  = blockIdx.x;
    const int lane = threadIdx.x;
    const float* p = mw + (size_t)idx * HIDDEN;
    float s = 0.f;
#pragma unroll
    for (int u = 0; u < 16; u++) { float v = p[u * 32 + lane]; s += v * v; }
    s = warpSum(s);
    if (lane == 0) g_yy[idx] = s;
}

// ---------------------------------------------------------------------------
// Mobius aggregation (NB=1 winner): one block per batch element, 9 warps.
// Output stored tf32-rounded AND k-permuted (consumed only by GEMM2-PERM).
// ---------------------------------------------------------------------------
__device__ const int d_ncnt[9]   = {3, 3, 2, 3, 3, 2, 3, 3, 8};
__device__ const int d_nbr[9][8] = {
    {4, 7, 8, 0, 0, 0, 0, 0},
    {0, 6, 8, 0, 0, 0, 0, 0},
    {5, 8, 0, 0, 0, 0, 0, 0},
    {1, 4, 8, 0, 0, 0, 0, 0},
    {6, 3, 8, 0, 0, 0, 0, 0},
    {2, 8, 0, 0, 0, 0, 0, 0},
    {7, 1, 8, 0, 0, 0, 0, 0},
    {3, 0, 8, 0, 0, 0, 0, 0},
    {0, 1, 2, 3, 4, 5, 6, 7}
};

__global__ __launch_bounds__(288)
void mobius_kernel(float* __restrict__ buf,
                   const float* __restrict__ mw,
                   const float* __restrict__ curv)
{
    __shared__ __align__(16) float sh[NUM_NODES * HIDDEN];
    __shared__ float sh_xx[NUM_NODES];

    const int b   = blockIdx.x;
    const int tid = threadIdx.x;
    const float c = fabsf(curv[0]);
    float* base = buf + (size_t)b * NUM_NODES * HIDDEN;

    for (int idx = tid; idx < NUM_NODES * HIDDEN / 4; idx += 288)
        ((float4*)sh)[idx] = ((const float4*)base)[idx];
    __syncthreads();

    const int w    = tid >> 5;
    const int lane = tid & 31;

    float r[16];
    float n2 = 0.f;
#pragma unroll
    for (int u = 0; u < 16; u++) {
        r[u] = sh[w * HIDDEN + u * 32 + lane];
        n2 += r[u] * r[u];
    }
    n2 = warpSum(n2);
    float norm  = sqrtf(n2);
    float scale = tanhf(norm) / (norm + EPS);
    float rr = scale * scale * n2;
#pragma unroll
    for (int u = 0; u < 16; u++) {
        r[u] *= scale;
        sh[w * HIDDEN + u * 32 + lane] = r[u];
    }
    if (lane == 0) sh_xx[w] = rr;
    __syncthreads();

    const int cnt = d_ncnt[w];
    for (int q = 0; q < cnt; q++) {
        const int j = d_nbr[w][q];
        const float* mwp = mw + ((size_t)w * NUM_NODES + j) * HIDDEN;
        const float yy = __ldg(&g_yy[w * NUM_NODES + j]);

        float hj[16], mv[16];
        float xy = 0.f;
#pragma unroll
        for (int u = 0; u < 16; u++) {
            hj[u] = sh[j * HIDDEN + u * 32 + lane];
            mv[u] = __ldg(&mwp[u * 32 + lane]);
            xy += hj[u] * mv[u];
        }
        xy = warpSum(xy);
        const float xxj = sh_xx[j];

        const float ca  = 1.f + 2.f * c * xy + c * yy;
        const float cb  = 1.f - c * xxj;
        const float inv = 1.f / (1.f + 2.f * c * xy + c * c * xxj * yy + EPS);
        const float tt  = inv * inv * (ca * ca * xxj + 2.f * ca * cb * xy + cb * cb * yy);

        float t[16];
        float rt = 0.f;
#pragma unroll
        for (int u = 0; u < 16; u++) {
            t[u] = (ca * hj[u] + cb * mv[u]) * inv;
            rt += r[u] * t[u];
        }
        rt = warpSum(rt);

        const float ca2  = 1.f + 2.f * c * rt + c * tt;
        const float cb2  = 1.f - c * rr;
        const float inv2 = 1.f / (1.f + 2.f * c * rt + c * c * rr * tt + EPS);
#pragma unroll
        for (int u = 0; u < 16; u++)
            r[u] = (ca2 * r[u] + cb2 * t[u]) * inv2;
        rr = inv2 * inv2 * (ca2 * ca2 * rr + 2.f * ca2 * cb2 * rt + cb2 * cb2 * tt);
    }

    // store tf32-rounded, k-permuted (pairs (k,k+4) adjacent) for GEMM2
    const int pos   = kperm(lane & 7);
    const int plane = (lane & 24) | pos;
    float* dst = base + (size_t)w * HIDDEN;
#pragma unroll
    for (int u = 0; u < 16; u++)
        dst[u * 32 + plane] = __uint_as_float(cvt_tf32(r[u]));
}

// ---------------------------------------------------------------------------
// kernel_launch: 8 chunks round-robin on 4 streams (proven-safe footprint),
// G1 chain-staggered across chunks.
// ---------------------------------------------------------------------------
extern "C" void kernel_launch(void* const* d_in, const int* in_sizes, int n_in,
                              void* d_out, int out_size)
{
    const float* nf     = (const float*)d_in[0];
    const float* curv   = (const float*)d_in[1];
    const float* to_w   = (const float*)d_in[2];
    const float* to_b   = (const float*)d_in[3];
    const float* from_w = (const float*)d_in[4];
    const float* from_b = (const float*)d_in[5];
    const float* mw     = (const float*)d_in[6];
    float* out = (float*)d_out;

    float *scratch, *w1, *w2;
    cudaGetSymbolAddress((void**)&scratch, g_scratch);
    cudaGetSymbolAddress((void**)&w1,      g_w1);
    cudaGetSymbolAddress((void**)&w2,      g_w2);

    cudaFuncSetAttribute((const void*)gemm_cp<true, false>,
                         cudaFuncAttributeMaxDynamicSharedMemorySize, DYN_SMEM_G1);
    cudaFuncSetAttribute((const void*)gemm_cp<false, true>,
                         cudaFuncAttributeMaxDynamicSharedMemorySize, DYN_SMEM_G2);

    // Prepasses on the origin (capture) stream.
    round_kernel<<<128, 256>>>((const float4*)to_w, (float4*)w1, HIDDEN * HIDDEN / 4);
    round_perm_kernel<<<256, 256>>>(from_w, w2, HIDDEN * HIDDEN);
    yy_kernel<<<NUM_NODES * NUM_NODES, 32>>>(mw);

    cudaStream_t s[NSTREAMS];
    cudaEvent_t  eFork, eJoin[NSTREAMS], eG1[NCHUNKS];
    cudaEventCreateWithFlags(&eFork, cudaEventDisableTiming);
    cudaEventRecord(eFork, 0);
    for (int i = 0; i < NSTREAMS; i++) {
        cudaStreamCreateWithFlags(&s[i], cudaStreamNonBlocking);
        cudaEventCreateWithFlags(&eJoin[i], cudaEventDisableTiming);
        cudaStreamWaitEvent(s[i], eFork, 0);
    }
    for (int k = 0; k < NCHUNKS; k++)
        cudaEventCreateWithFlags(&eG1[k], cudaEventDisableTiming);

    dim3 gg(HIDDEN / BN, ROWS_PER_CHUNK / BM);   // (4, 72)

    for (int k = 0; k < NCHUNKS; k++) {
        cudaStream_t st = s[k % NSTREAMS];
        const size_t rowOff = (size_t)k * ROWS_PER_CHUNK;
        const float* aPtr = nf      + rowOff * HIDDEN;
        float*       sPtr = scratch + rowOff * HIDDEN;
        float*       oPtr = out     + rowOff * HIDDEN;

        // Stagger: chunk k's G1 after chunk k-1's G1 (cross-stream chain).
        if (k > 0) cudaStreamWaitEvent(st, eG1[k - 1], 0);

        gemm_cp<true, false><<<gg, 128, DYN_SMEM_G1, st>>>(aPtr, w1, to_b, sPtr);
        cudaEventRecord(eG1[k], st);

        mobius_kernel<<<BATCH_PER_CHUNK, 288, 0, st>>>(sPtr, mw, curv);
        gemm_cp<false, true><<<gg, 128, DYN_SMEM_G2, st>>>(sPtr, w2, from_b, oPtr);
    }

    for (int i = 0; i < NSTREAMS; i++) {
        cudaEventRecord(eJoin[i], s[i]);
        cudaStreamWaitEvent(0, eJoin[i], 0);
    }

    for (int i = 0; i < NSTREAMS; i++) {
        cudaStreamDestroy(s[i]);
        cudaEventDestroy(eJoin[i]);
    }
    for (int k = 0; k < NCHUNKS; k++)
        cudaEventDestroy(eG1[k]);
    cudaEventDestroy(eFork);
}